// round 2
// baseline (speedup 1.0000x reference)
#include <cuda_runtime.h>
#include <cuda_bf16.h>
#include <math.h>

#define M_LIB   200000
#define N_PATCH 676
#define NPAD    768
#define DIM     384
#define KSTEPS  24
#define BM      64
#define STRIPE  5440
#define IMG     224
#define SIGMA   4.0f
#define KRAD    16

#define PITCH      784
#define SP_LIB_OFF (192*PITCH)
#define SP_MIN_OFF (SP_LIB_OFF + 64*PITCH)
#define SMEM_MAIN  (SP_MIN_OFF + 192*8)

__device__ __align__(16) __nv_bfloat16 g_lib_bf16[(size_t)M_LIB * DIM];
__device__ float g_ln[M_LIB];
__device__ float g_patch_n[N_PATCH * DIM];
__device__ __align__(16) __nv_bfloat16 g_patch_bf16[NPAD * DIM];
__device__ float g_pn[N_PATCH];
__device__ unsigned long long g_minbuf[NPAD];
__device__ float g_minval[N_PATCH];
__device__ int   g_sidx;
__device__ int   g_mstar_idx;
__device__ float g_sstar;
__device__ float g_d2star[M_LIB];
__device__ unsigned long long g_btop[64 * 5];
__device__ int   g_nn[5];
__device__ float g_map_a[IMG * IMG];
__device__ float g_map_b[IMG * IMG];

__device__ __forceinline__ unsigned fordu(float f) {
    unsigned u = __float_as_uint(f);
    return (u & 0x80000000u) ? ~u : (u | 0x80000000u);
}
__device__ __forceinline__ float fordu_inv(unsigned e) {
    return __uint_as_float((e & 0x80000000u) ? (e ^ 0x80000000u) : ~e);
}
__device__ __forceinline__ unsigned long long packkey(float v, int idx) {
    return ((unsigned long long)fordu(v) << 32) | (unsigned)idx;
}
__device__ __forceinline__ unsigned long long ullmin2(unsigned long long a, unsigned long long b) {
    return a < b ? a : b;
}
#define INF_F (__int_as_float(0x7f800000))

#define LDSM4(r0,r1,r2,r3,addr) \
    asm volatile("ldmatrix.sync.aligned.m8n8.x4.shared.b16 {%0,%1,%2,%3}, [%4];" \
        : "=r"(r0), "=r"(r1), "=r"(r2), "=r"(r3) : "r"(addr))
#define MMA16816(D,a0,a1,a2,a3,b0,b1) \
    asm volatile("mma.sync.aligned.m16n8k16.row.col.f32.bf16.bf16.f32 " \
        "{%0,%1,%2,%3},{%4,%5,%6,%7},{%8,%9},{%0,%1,%2,%3};" \
        : "+f"((D)[0]), "+f"((D)[1]), "+f"((D)[2]), "+f"((D)[3]) \
        : "r"(a0), "r"(a1), "r"(a2), "r"(a3), "r"(b0), "r"(b1))

// 1. normalize patch -> fp32 + bf16 (zero pad to 768 rows), pn
__global__ void k_prep_patch(const float* __restrict__ patch) {
    int n = blockIdx.x, t = threadIdx.x;  // 128 thr
    if (n >= N_PATCH) {
        #pragma unroll
        for (int j = 0; j < 3; j++) g_patch_bf16[n * DIM + t + 128 * j] = __float2bfloat16(0.f);
        return;
    }
    __shared__ float red[128];
    float v[3]; float ss = 0.f;
    #pragma unroll
    for (int j = 0; j < 3; j++) { v[j] = patch[(size_t)n * DIM + t + 128 * j]; ss += v[j] * v[j]; }
    red[t] = ss; __syncthreads();
    for (int s = 64; s > 0; s >>= 1) { if (t < s) red[t] += red[t + s]; __syncthreads(); }
    float denom = fmaxf(sqrtf(red[0]), 1e-12f);
    __syncthreads();
    float pn = 0.f;
    #pragma unroll
    for (int j = 0; j < 3; j++) {
        float x = v[j] / denom; pn += x * x;
        g_patch_n[n * DIM + t + 128 * j] = x;
        g_patch_bf16[n * DIM + t + 128 * j] = __float2bfloat16(x);
    }
    red[t] = pn; __syncthreads();
    for (int s = 64; s > 0; s >>= 1) { if (t < s) red[t] += red[t + s]; __syncthreads(); }
    if (t == 0) g_pn[n] = red[0];
}

// 2. lib fp32 -> bf16 + ln
__global__ void k_prep_lib(const float* __restrict__ lib) {
    int w = threadIdx.x >> 5, lane = threadIdx.x & 31;
    int row = blockIdx.x * 8 + w;
    const float4* src = (const float4*)(lib + (size_t)row * DIM);
    __nv_bfloat162* dst = (__nv_bfloat162*)(g_lib_bf16 + (size_t)row * DIM);
    float ss = 0.f;
    #pragma unroll
    for (int j = 0; j < 3; j++) {
        float4 f = src[lane + 32 * j];
        ss += f.x * f.x + f.y * f.y + f.z * f.z + f.w * f.w;
        dst[2 * (lane + 32 * j)]     = __floats2bfloat162_rn(f.x, f.y);
        dst[2 * (lane + 32 * j) + 1] = __floats2bfloat162_rn(f.z, f.w);
    }
    for (int o = 16; o; o >>= 1) ss += __shfl_xor_sync(0xffffffffu, ss, o);
    if (lane == 0) g_ln[row] = ss;
}

__global__ void k_init() {
    for (int i = threadIdx.x; i < NPAD; i += blockDim.x) g_minbuf[i] = ~0ull;
}

// 4. fused bf16 GEMM + per-column (min, argmin)
__global__ void __launch_bounds__(256, 1) k_main() {
    extern __shared__ char sm[];
    char* sPatchB = sm;
    char* sLibB   = sm + SP_LIB_OFF;
    unsigned long long* sMin = (unsigned long long*)(sm + SP_MIN_OFF);
    const int tid = threadIdx.x;
    const int nc = blockIdx.x & 3, stripe = blockIdx.x >> 2;
    if (tid < 192) sMin[tid] = ~0ull;
    {   // stage resident patch chunk [192 x 384] bf16
        const int4* src = (const int4*)(g_patch_bf16 + (size_t)nc * 192 * DIM);
        for (int i = tid; i < 192 * 48; i += 256)
            *(int4*)(sPatchB + (i / 48) * PITCH + (i % 48) * 16) = src[i];
    }
    const int warp = tid >> 5, lane = tid & 31;
    const int wm = warp & 3, wn = warp >> 2;
    const int g8 = lane >> 2, tig = lane & 3;
    unsigned aOff  = (unsigned)((16 * wm + (lane & 15)) * PITCH + (lane >> 4) * 16);
    unsigned bRow  = (lane & 7) + ((lane >> 4) << 3);
    unsigned bKofs = ((lane >> 3) & 1) * 16;
    unsigned sLibAddr   = (unsigned)__cvta_generic_to_shared(sLibB);
    unsigned sPatchAddr = (unsigned)__cvta_generic_to_shared(sPatchB);

    float runV[24]; int runI[24];
    #pragma unroll
    for (int j = 0; j < 24; j++) { runV[j] = INF_F; runI[j] = 0; }

    int mStart = stripe * STRIPE;
    int mEnd = min(mStart + STRIPE, M_LIB);
    for (int mt = mStart; mt < mEnd; mt += BM) {
        __syncthreads();
        for (int i = tid; i < 64 * 48; i += 256) {
            int r = i / 48, c = i % 48, m = mt + r;
            int4 val = make_int4(0, 0, 0, 0);
            if (m < M_LIB) val = *(const int4*)(g_lib_bf16 + (size_t)m * DIM + c * 8);
            *(int4*)(sLibB + r * PITCH + c * 16) = val;
        }
        __syncthreads();
        float acc[12][4];
        #pragma unroll
        for (int f = 0; f < 12; f++) acc[f][0] = acc[f][1] = acc[f][2] = acc[f][3] = 0.f;
        #pragma unroll 1
        for (int ks = 0; ks < KSTEPS; ks++) {
            unsigned kb = (unsigned)ks * 32u;
            unsigned a0, a1, a2, a3;
            LDSM4(a0, a1, a2, a3, sLibAddr + aOff + kb);
            #pragma unroll
            for (int j6 = 0; j6 < 6; j6++) {
                unsigned r0, r1, r2, r3;
                LDSM4(r0, r1, r2, r3,
                      sPatchAddr + (96 * wn + 16 * j6 + bRow) * PITCH + kb + bKofs);
                MMA16816(acc[2 * j6],     a0, a1, a2, a3, r0, r1);
                MMA16816(acc[2 * j6 + 1], a0, a1, a2, a3, r2, r3);
            }
        }
        int mlo = mt + 16 * wm + g8, mhi = mlo + 8;
        float lnlo = (mlo < M_LIB) ? g_ln[mlo] : INF_F;
        float lnhi = (mhi < M_LIB) ? g_ln[mhi] : INF_F;
        #pragma unroll
        for (int f = 0; f < 12; f++) {
            #pragma unroll
            for (int c = 0; c < 2; c++) {
                int j = 2 * f + c;
                float slo = fmaf(-2.f, acc[f][c],     lnlo);
                float shi = fmaf(-2.f, acc[f][2 + c], lnhi);
                if (slo < runV[j]) { runV[j] = slo; runI[j] = mlo; }
                if (shi < runV[j]) { runV[j] = shi; runI[j] = mhi; }
            }
        }
    }
    #pragma unroll
    for (int off = 4; off < 32; off <<= 1) {
        #pragma unroll
        for (int j = 0; j < 24; j++) {
            float ov = __shfl_xor_sync(0xffffffffu, runV[j], off);
            int   oi = __shfl_xor_sync(0xffffffffu, runI[j], off);
            if (ov < runV[j]) { runV[j] = ov; runI[j] = oi; }
        }
    }
    if (g8 == 0) {
        #pragma unroll
        for (int j = 0; j < 24; j++) {
            int cl = 96 * wn + 8 * (j >> 1) + 2 * tig + (j & 1);
            atomicMin(&sMin[cl], packkey(runV[j], runI[j]));
        }
    }
    __syncthreads();
    if (tid < 192) atomicMin(&g_minbuf[nc * 192 + tid], sMin[tid]);
}

// 5. min_val per n + argmax over n
__global__ void k_nmin() {
    int t = threadIdx.x;  // 1024
    __shared__ float rv[1024]; __shared__ int ri[1024];
    float mv = -INF_F; int idx = 0;
    if (t < N_PATCH) {
        unsigned long long key = g_minbuf[t];
        float d2 = g_pn[t] + fordu_inv((unsigned)(key >> 32));
        mv = sqrtf(fmaxf(d2, 0.f));
        g_minval[t] = mv; idx = t;
    }
    rv[t] = mv; ri[t] = idx; __syncthreads();
    for (int s = 512; s > 0; s >>= 1) {
        if (t < s && rv[t + s] > rv[t]) { rv[t] = rv[t + s]; ri[t] = ri[t + s]; }
        __syncthreads();
    }
    if (t == 0) {
        g_sidx = ri[0]; g_sstar = rv[0];
        g_mstar_idx = (int)(g_minbuf[ri[0]] & 0xffffffffu);
    }
}

// 6. shifted d*^2 over all lib rows (ordering-equivalent)
__global__ void k_pass2() {
    int w = threadIdx.x >> 5, lane = threadIdx.x & 31;
    int row = blockIdx.x * 8 + w;
    int msi = g_mstar_idx;
    const unsigned* a = (const unsigned*)(g_lib_bf16 + (size_t)row * DIM);
    const unsigned* b = (const unsigned*)(g_lib_bf16 + (size_t)msi * DIM);
    float dot = 0.f;
    #pragma unroll
    for (int j = 0; j < 6; j++) {
        unsigned ua = a[lane + 32 * j], ub = b[lane + 32 * j];
        float2 fa = __bfloat1622float2(*(__nv_bfloat162*)&ua);
        float2 fb = __bfloat1622float2(*(__nv_bfloat162*)&ub);
        dot = fmaf(fa.x, fb.x, dot); dot = fmaf(fa.y, fb.y, dot);
    }
    for (int o = 16; o; o >>= 1) dot += __shfl_xor_sync(0xffffffffu, dot, o);
    if (lane == 0) g_d2star[row] = g_ln[row] - 2.f * dot;
}

// 7. top-5 smallest, block stage
__global__ void k_topscan() {
    unsigned long long best[5];
    #pragma unroll
    for (int r = 0; r < 5; r++) best[r] = ~0ull;
    for (int m = blockIdx.x * 256 + threadIdx.x; m < M_LIB; m += 64 * 256) {
        unsigned long long key = packkey(g_d2star[m], m);
        if (key < best[4]) {
            best[4] = key;
            #pragma unroll
            for (int r = 4; r > 0; r--)
                if (best[r] < best[r - 1]) { unsigned long long tm = best[r]; best[r] = best[r - 1]; best[r - 1] = tm; }
        }
    }
    __shared__ unsigned long long sb[5 * 256], red[256], winner;
    int t = threadIdx.x;
    #pragma unroll
    for (int r = 0; r < 5; r++) sb[r * 256 + t] = best[r];
    __syncthreads();
    for (int round = 0; round < 5; round++) {
        unsigned long long mn = ~0ull;
        #pragma unroll
        for (int r = 0; r < 5; r++) mn = ullmin2(mn, sb[r * 256 + t]);
        red[t] = mn; __syncthreads();
        for (int s = 128; s > 0; s >>= 1) { if (t < s) red[t] = ullmin2(red[t], red[t + s]); __syncthreads(); }
        if (t == 0) { winner = red[0]; g_btop[blockIdx.x * 5 + round] = red[0]; }
        __syncthreads();
        unsigned long long wv = winner;
        #pragma unroll
        for (int r = 0; r < 5; r++) if (sb[r * 256 + t] == wv) sb[r * 256 + t] = ~0ull;
        __syncthreads();
    }
}

// 8. top-5 final merge
__global__ void k_topfinal() {
    __shared__ unsigned long long sb[320], red[256], winner;
    int t = threadIdx.x;  // 256
    sb[t] = g_btop[t];
    if (t < 64) sb[256 + t] = g_btop[256 + t];
    __syncthreads();
    for (int round = 0; round < 5; round++) {
        unsigned long long mn = sb[t];
        if (t < 64) mn = ullmin2(mn, sb[256 + t]);
        red[t] = mn; __syncthreads();
        for (int s = 128; s > 0; s >>= 1) { if (t < s) red[t] = ullmin2(red[t], red[t + s]); __syncthreads(); }
        if (t == 0) { winner = red[0]; g_nn[round] = (int)(red[0] & 0xffffffffu); }
        __syncthreads();
        unsigned long long wv = winner;
        if (sb[t] == wv) sb[t] = ~0ull;
        if (t < 64 && sb[256 + t] == wv) sb[256 + t] = ~0ull;
        __syncthreads();
    }
}

// 9. scalar s (fp32 exact vectors)
__global__ void k_scalar(const float* __restrict__ lib, float* __restrict__ out, int write_s) {
    __shared__ float red[6][128];
    int t = threadIdx.x;  // 128
    int sidx = g_sidx, msi = g_mstar_idx;
    int nn[5];
    #pragma unroll
    for (int i = 0; i < 5; i++) nn[i] = g_nn[i];
    float ss[6] = {0.f, 0.f, 0.f, 0.f, 0.f, 0.f};
    #pragma unroll
    for (int j = 0; j < 3; j++) {
        int col = t + 128 * j;
        float p = g_patch_n[sidx * DIM + col];
        float d0 = p - lib[(size_t)msi * DIM + col];
        ss[0] += d0 * d0;
        #pragma unroll
        for (int i = 0; i < 5; i++) {
            float d = p - lib[(size_t)nn[i] * DIM + col];
            ss[1 + i] += d * d;
        }
    }
    #pragma unroll
    for (int q = 0; q < 6; q++) red[q][t] = ss[q];
    __syncthreads();
    for (int s = 64; s > 0; s >>= 1) {
        if (t < s) {
            #pragma unroll
            for (int q = 0; q < 6; q++) red[q][t] += red[q][t + s];
        }
        __syncthreads();
    }
    if (t == 0 && write_s) {
        float num = expf(sqrtf(red[0][0]));
        float den = 0.f;
        #pragma unroll
        for (int i = 0; i < 5; i++) den += expf(sqrtf(red[1 + i][0]));
        out[0] = (1.f - num / den) * g_sstar;
    }
}

// 10. bilinear 26 -> 224 (half-pixel, clamp)
__global__ void k_upsample() {
    int x = blockIdx.x * 32 + threadIdx.x;
    int y = blockIdx.y * 8 + threadIdx.y;
    if (x >= IMG || y >= IMG) return;
    const float scale = 26.f / 224.f;
    float sx = (x + 0.5f) * scale - 0.5f;
    float sy = (y + 0.5f) * scale - 0.5f;
    int x0 = (int)floorf(sx), y0 = (int)floorf(sy);
    float fx = sx - x0, fy = sy - y0;
    int x0c = min(max(x0, 0), 25), x1c = min(max(x0 + 1, 0), 25);
    int y0c = min(max(y0, 0), 25), y1c = min(max(y0 + 1, 0), 25);
    float v00 = g_minval[y0c * 26 + x0c], v01 = g_minval[y0c * 26 + x1c];
    float v10 = g_minval[y1c * 26 + x0c], v11 = g_minval[y1c * 26 + x1c];
    float top = v00 + fx * (v01 - v00), bot = v10 + fx * (v11 - v10);
    g_map_a[y * IMG + x] = top + fy * (bot - top);
}

__device__ __forceinline__ int reflect_idx(int j) {
    if (j < 0) j = -j;
    if (j > IMG - 1) j = 2 * (IMG - 1) - j;
    return j;
}
__device__ __forceinline__ void blur_weights(float* w) {
    float s = 0.f;
    #pragma unroll
    for (int i = 0; i < 33; i++) {
        float xx = (float)(i - KRAD) / SIGMA;
        w[i] = expf(-0.5f * xx * xx); s += w[i];
    }
    float inv = 1.f / s;
    #pragma unroll
    for (int i = 0; i < 33; i++) w[i] *= inv;
}
// 11a. vertical blur (reference applies kh first)
__global__ void k_blur_v() {
    int x = blockIdx.x * 32 + threadIdx.x;
    int y = blockIdx.y * 8 + threadIdx.y;
    if (x >= IMG || y >= IMG) return;
    float w[33]; blur_weights(w);
    float acc = 0.f;
    #pragma unroll
    for (int i = 0; i < 33; i++) acc += w[i] * g_map_a[reflect_idx(y + i - KRAD) * IMG + x];
    g_map_b[y * IMG + x] = acc;
}
// 11b. horizontal blur -> out
__global__ void k_blur_h(float* __restrict__ out) {
    int x = blockIdx.x * 32 + threadIdx.x;
    int y = blockIdx.y * 8 + threadIdx.y;
    if (x >= IMG || y >= IMG) return;
    float w[33]; blur_weights(w);
    float acc = 0.f;
    #pragma unroll
    for (int i = 0; i < 33; i++) acc += w[i] * g_map_b[y * IMG + reflect_idx(x + i - KRAD)];
    out[y * IMG + x] = acc;
}

extern "C" void kernel_launch(void* const* d_in, const int* in_sizes, int n_in,
                              void* d_out, int out_size) {
    const float* patch = (const float*)d_in[0];
    const float* lib   = (const float*)d_in[1];
    if (n_in >= 2 && in_sizes[0] != N_PATCH * DIM) {  // defensive order check
        patch = (const float*)d_in[1]; lib = (const float*)d_in[0];
    }
    float* out = (float*)d_out;
    int ofs = out_size - IMG * IMG;
    if (ofs < 0) ofs = 0;

    static int smem_set = 0;
    if (!smem_set) {
        cudaFuncSetAttribute(k_main, cudaFuncAttributeMaxDynamicSharedMemorySize, SMEM_MAIN);
        smem_set = 1;
    }

    k_prep_patch<<<NPAD, 128>>>(patch);
    k_prep_lib<<<M_LIB / 8, 256>>>(lib);
    k_init<<<1, 768>>>();
    k_main<<<148, 256, SMEM_MAIN>>>();
    k_nmin<<<1, 1024>>>();
    k_pass2<<<M_LIB / 8, 256>>>();
    k_topscan<<<64, 256>>>();
    k_topfinal<<<1, 256>>>();
    k_scalar<<<1, 128>>>(lib, out, ofs > 0 ? 1 : 0);
    dim3 blk(32, 8), grd(7, 28);
    k_upsample<<<grd, blk>>>();
    k_blur_v<<<grd, blk>>>();
    k_blur_h<<<grd, blk>>>(out + ofs);
}

// round 4
// speedup vs baseline: 1.2416x; 1.2416x over previous
#include <cuda_runtime.h>
#include <cuda_bf16.h>
#include <math.h>
#include <stdint.h>

#define M_LIB   200000
#define N_PATCH 676
#define NPAD    768
#define DIM     384
#define IMG     224
#define SIGMA   4.0f
#define KRAD    16

#define STRIPE  5440            // 64 * 85 rows per CTA stripe; 37 stripes
#define NTILES  85
#define NITERS  170             // 85 tiles * 2 k-halves
#define STG_BYTES (64*384)      // one stage: 64 rows x 192 k-elems bf16
#define SM_P    0               // patch chunk 192 x 768B = 147456
#define SM_L    147456
#define SM_MIN  (SM_L + 3*STG_BYTES)   // 221184
#define SMEM_MAIN (SM_MIN + 192*8)     // 222720

// ---------------- device scratch ----------------
__device__ __align__(16) __nv_bfloat16 g_lib_bf16[(size_t)M_LIB * DIM];
__device__ float g_ln[M_LIB];
__device__ float g_patch_n[N_PATCH * DIM];
__device__ __align__(16) __nv_bfloat16 g_patch_bf16[NPAD * DIM];
__device__ float g_pn[N_PATCH];
__device__ unsigned long long g_minbuf[NPAD];
__device__ float g_minval[N_PATCH];
__device__ int   g_sidx;
__device__ int   g_mstar_idx;
__device__ float g_sstar;
__device__ float g_d2star[M_LIB];
__device__ unsigned long long g_btop[64 * 5];
__device__ int   g_nn[5];
__device__ float g_map_a[IMG * IMG];
__device__ float g_map_b[IMG * IMG];

// ---------------- helpers ----------------
__device__ __forceinline__ unsigned fordu(float f) {
    unsigned u = __float_as_uint(f);
    return (u & 0x80000000u) ? ~u : (u | 0x80000000u);
}
__device__ __forceinline__ float fordu_inv(unsigned e) {
    return __uint_as_float((e & 0x80000000u) ? (e ^ 0x80000000u) : ~e);
}
__device__ __forceinline__ unsigned long long packkey(float v, int idx) {
    return ((unsigned long long)fordu(v) << 32) | (unsigned)idx;
}
__device__ __forceinline__ unsigned long long ullmin2(unsigned long long a, unsigned long long b) {
    return a < b ? a : b;
}
#define INF_F (__int_as_float(0x7f800000))

__device__ __forceinline__ uint32_t smem_u32(const void* p) {
    return (uint32_t)__cvta_generic_to_shared(p);
}

#define LDSM4(r0,r1,r2,r3,addr) \
    asm volatile("ldmatrix.sync.aligned.m8n8.x4.shared.b16 {%0,%1,%2,%3}, [%4];" \
        : "=r"(r0), "=r"(r1), "=r"(r2), "=r"(r3) : "r"(addr))
#define MMA16816(D,a0,a1,a2,a3,b0,b1) \
    asm volatile("mma.sync.aligned.m16n8k16.row.col.f32.bf16.bf16.f32 " \
        "{%0,%1,%2,%3},{%4,%5,%6,%7},{%8,%9},{%0,%1,%2,%3};" \
        : "+f"((D)[0]), "+f"((D)[1]), "+f"((D)[2]), "+f"((D)[3]) \
        : "r"(a0), "r"(a1), "r"(a2), "r"(a3), "r"(b0), "r"(b1))

__device__ __forceinline__ void cp16(uint32_t dst, const void* src, uint32_t nbytes) {
    asm volatile("cp.async.cg.shared.global [%0], [%1], 16, %2;"
                 :: "r"(dst), "l"(src), "r"(nbytes) : "memory");
}
#define CP_COMMIT() asm volatile("cp.async.commit_group;" ::: "memory")
#define CP_WAIT1()  asm volatile("cp.async.wait_group 1;" ::: "memory")

// ---------------- 1. normalize patch ----------------
__global__ void k_prep_patch(const float* __restrict__ patch) {
    int n = blockIdx.x, t = threadIdx.x;  // 128 thr
    if (n >= N_PATCH) {
        #pragma unroll
        for (int j = 0; j < 3; j++) g_patch_bf16[n * DIM + t + 128 * j] = __float2bfloat16(0.f);
        return;
    }
    __shared__ float red[128];
    float v[3]; float ss = 0.f;
    #pragma unroll
    for (int j = 0; j < 3; j++) { v[j] = patch[(size_t)n * DIM + t + 128 * j]; ss += v[j] * v[j]; }
    red[t] = ss; __syncthreads();
    for (int s = 64; s > 0; s >>= 1) { if (t < s) red[t] += red[t + s]; __syncthreads(); }
    float denom = fmaxf(sqrtf(red[0]), 1e-12f);
    __syncthreads();
    float pn = 0.f;
    #pragma unroll
    for (int j = 0; j < 3; j++) {
        float x = v[j] / denom; pn += x * x;
        g_patch_n[n * DIM + t + 128 * j] = x;
        g_patch_bf16[n * DIM + t + 128 * j] = __float2bfloat16(x);
    }
    red[t] = pn; __syncthreads();
    for (int s = 64; s > 0; s >>= 1) { if (t < s) red[t] += red[t + s]; __syncthreads(); }
    if (t == 0) g_pn[n] = red[0];
}

// ---------------- 2. lib fp32 -> bf16 + ln ----------------
__global__ void k_prep_lib(const float* __restrict__ lib) {
    int w = threadIdx.x >> 5, lane = threadIdx.x & 31;
    int row = blockIdx.x * 8 + w;
    const float4* src = (const float4*)(lib + (size_t)row * DIM);
    __nv_bfloat162* dst = (__nv_bfloat162*)(g_lib_bf16 + (size_t)row * DIM);
    float ss = 0.f;
    #pragma unroll
    for (int j = 0; j < 3; j++) {
        float4 f = src[lane + 32 * j];
        ss += f.x * f.x + f.y * f.y + f.z * f.z + f.w * f.w;
        dst[2 * (lane + 32 * j)]     = __floats2bfloat162_rn(f.x, f.y);
        dst[2 * (lane + 32 * j) + 1] = __floats2bfloat162_rn(f.z, f.w);
    }
    for (int o = 16; o; o >>= 1) ss += __shfl_xor_sync(0xffffffffu, ss, o);
    if (lane == 0) g_ln[row] = ss;
}

__global__ void k_init() {
    for (int i = threadIdx.x; i < NPAD; i += blockDim.x) g_minbuf[i] = ~0ull;
}

// ---------------- 4. fused bf16 HMMA GEMM + per-patch-row max-dot ----------
// grid 148 = 4 n-chunks x 37 stripes; 512 threads.
// A = lib rows (m, streamed 64 rows x k-half via cp.async, 3 stages)
// B = patch chunk (192 n-rows x 384 k, resident, XOR-swizzled)
__global__ void __launch_bounds__(512, 1) k_main() {
    extern __shared__ char sm[];
    const uint32_t smb = smem_u32(sm);
    unsigned long long* sMin = (unsigned long long*)(sm + SM_MIN);
    const int tid = threadIdx.x;
    const int warp = tid >> 5, lane = tid & 31;
    const int nc = blockIdx.x & 3;
    const int mBase = (blockIdx.x >> 2) * STRIPE;

    if (tid < 192) sMin[tid] = ~0ull;

    // --- stage resident patch chunk [192 x 384] bf16, swizzled 768B rows ---
    for (int i = tid; i < 192 * 48; i += 512) {
        int r = i / 48, u = i % 48;
        uint32_t dst = smb + SM_P + r * 768 + (((u ^ (r & 7))) << 4);
        cp16(dst, g_patch_bf16 + (size_t)(nc * 192 + r) * DIM + u * 8, 16);
    }
    CP_COMMIT();

    // --- prologue: stages 0,1 = tile0 half0, half1 ---
    #pragma unroll
    for (int p = 0; p < 2; p++) {
        for (int i = tid; i < 64 * 24; i += 512) {
            int r = i / 24, u = i % 24;
            int g = mBase + r;
            uint32_t dst = smb + SM_L + p * STG_BYTES + r * 384 + (((u ^ (r & 7))) << 4);
            cp16(dst, g_lib_bf16 + (size_t)min(g, M_LIB - 1) * DIM + p * 192 + u * 8,
                 (g < M_LIB) ? 16u : 0u);
        }
        CP_COMMIT();
    }

    // --- per-thread invariants ---
    const int wm = warp & 3, wn = warp >> 2;      // warp tile: 16m x 48n
    const unsigned rA = 16 * wm + (lane & 15);
    const unsigned baseA = rA * 384;
    const unsigned swA = rA & 7;
    const unsigned hiA = (lane >> 4);
    const unsigned hiB = (lane >> 3) & 1;
    unsigned pBase[3], swB[3];
    #pragma unroll
    for (int f2 = 0; f2 < 3; f2++) {
        unsigned rB = 48 * wn + 16 * f2 + (lane & 7) + ((lane >> 4) << 3);
        pBase[f2] = smb + SM_P + rB * 768;
        swB[f2] = rB & 7;
    }
    const int g8 = lane >> 2;

    float runV[12]; int runI[12];
    #pragma unroll
    for (int j = 0; j < 12; j++) { runV[j] = -INF_F; runI[j] = 0; }

    float acc[6][4];
    #pragma unroll
    for (int f = 0; f < 6; f++) acc[f][0] = acc[f][1] = acc[f][2] = acc[f][3] = 0.f;

    for (int it = 0; it < NITERS; it++) {
        const int s = it % 3, h = it & 1;
        CP_WAIT1();
        __syncthreads();
        // prefetch it+2 into freed stage
        {
            int nx = it + 2;
            if (nx < NITERS) {
                int sN = nx % 3, hN = nx & 1, mN = mBase + (nx >> 1) * 64;
                for (int i = tid; i < 64 * 24; i += 512) {
                    int r = i / 24, u = i % 24;
                    int g = mN + r;
                    uint32_t dst = smb + SM_L + sN * STG_BYTES + r * 384 + (((u ^ (r & 7))) << 4);
                    cp16(dst, g_lib_bf16 + (size_t)min(g, M_LIB - 1) * DIM + hN * 192 + u * 8,
                         (g < M_LIB) ? 16u : 0u);
                }
            }
            CP_COMMIT();
        }
        // compute this stage: 12 ksteps
        const unsigned stgA = smb + SM_L + s * STG_BYTES + baseA;
        const unsigned kb0 = 24 * h + hiB;
        #pragma unroll
        for (int ks = 0; ks < 12; ks++) {
            unsigned a0, a1, a2, a3;
            unsigned uA = 2 * ks + hiA;
            LDSM4(a0, a1, a2, a3, stgA + (((uA ^ swA)) << 4));
            #pragma unroll
            for (int f2 = 0; f2 < 3; f2++) {
                unsigned r0, r1, r2, r3;
                unsigned uB = kb0 + 2 * ks;
                LDSM4(r0, r1, r2, r3, pBase[f2] + (((uB ^ swB[f2])) << 4));
                MMA16816(acc[2 * f2],     a0, a1, a2, a3, r0, r1);
                MMA16816(acc[2 * f2 + 1], a0, a1, a2, a3, r2, r3);
            }
        }
        if (h) {
            // tile epilogue: update per-column running max dot
            int mt = mBase + (it >> 1) * 64;
            int mlo = mt + 16 * wm + g8, mhi = mlo + 8;
            bool okLo = mlo < M_LIB, okHi = mhi < M_LIB;
            #pragma unroll
            for (int f = 0; f < 6; f++) {
                #pragma unroll
                for (int c = 0; c < 2; c++) {
                    int j = 2 * f + c;
                    float vlo = acc[f][c], vhi = acc[f][2 + c];
                    if (okLo && vlo > runV[j]) { runV[j] = vlo; runI[j] = mlo; }
                    if (okHi && vhi > runV[j]) { runV[j] = vhi; runI[j] = mhi; }
                }
            }
            #pragma unroll
            for (int f = 0; f < 6; f++) acc[f][0] = acc[f][1] = acc[f][2] = acc[f][3] = 0.f;
        }
    }

    // reduce over the 8 lanes sharing each column
    #pragma unroll
    for (int off = 4; off < 32; off <<= 1) {
        #pragma unroll
        for (int j = 0; j < 12; j++) {
            float ov = __shfl_xor_sync(0xffffffffu, runV[j], off);
            int   oi = __shfl_xor_sync(0xffffffffu, runI[j], off);
            if (ov > runV[j]) { runV[j] = ov; runI[j] = oi; }
        }
    }
    if (g8 == 0) {
        #pragma unroll
        for (int j = 0; j < 12; j++) {
            int col = 48 * wn + 8 * (j >> 1) + 2 * lane + (j & 1);
            atomicMin(&sMin[col], packkey(-runV[j], runI[j]));
        }
    }
    __syncthreads();
    if (tid < 192) atomicMin(&g_minbuf[nc * 192 + tid], sMin[tid]);
}

// ---------------- 5. min_val per n + argmax over n ----------------
__global__ void k_nmin() {
    int t = threadIdx.x;  // 1024
    __shared__ float rv[1024]; __shared__ int ri[1024];
    float mv = -INF_F; int idx = 0;
    if (t < N_PATCH) {
        unsigned long long key = g_minbuf[t];
        int mi = (int)(key & 0xffffffffu);
        float v = fordu_inv((unsigned)(key >> 32));   // = -max_dot
        float d2 = g_pn[t] + g_ln[mi] + 2.f * v;
        mv = sqrtf(fmaxf(d2, 0.f));
        g_minval[t] = mv; idx = t;
    }
    rv[t] = mv; ri[t] = idx; __syncthreads();
    for (int s = 512; s > 0; s >>= 1) {
        if (t < s && rv[t + s] > rv[t]) { rv[t] = rv[t + s]; ri[t] = ri[t + s]; }
        __syncthreads();
    }
    if (t == 0) {
        g_sidx = ri[0]; g_sstar = rv[0];
        g_mstar_idx = (int)(g_minbuf[ri[0]] & 0xffffffffu);
    }
}

// ---------------- 6. d*^2 (shifted) over all lib rows ----------------
__global__ void k_pass2() {
    int w = threadIdx.x >> 5, lane = threadIdx.x & 31;
    int row = blockIdx.x * 8 + w;
    int msi = g_mstar_idx;
    const unsigned* a = (const unsigned*)(g_lib_bf16 + (size_t)row * DIM);
    const unsigned* b = (const unsigned*)(g_lib_bf16 + (size_t)msi * DIM);
    float dot = 0.f;
    #pragma unroll
    for (int j = 0; j < 6; j++) {
        unsigned ua = a[lane + 32 * j], ub = b[lane + 32 * j];
        float2 fa = __bfloat1622float2(*(__nv_bfloat162*)&ua);
        float2 fb = __bfloat1622float2(*(__nv_bfloat162*)&ub);
        dot = fmaf(fa.x, fb.x, dot); dot = fmaf(fa.y, fb.y, dot);
    }
    for (int o = 16; o; o >>= 1) dot += __shfl_xor_sync(0xffffffffu, dot, o);
    if (lane == 0) g_d2star[row] = g_ln[row] - 2.f * dot;
}

// ---------------- 7. top-5 smallest, block stage ----------------
__global__ void k_topscan() {
    unsigned long long best[5];
    #pragma unroll
    for (int r = 0; r < 5; r++) best[r] = ~0ull;
    for (int m = blockIdx.x * 256 + threadIdx.x; m < M_LIB; m += 64 * 256) {
        unsigned long long key = packkey(g_d2star[m], m);
        if (key < best[4]) {
            best[4] = key;
            #pragma unroll
            for (int r = 4; r > 0; r--)
                if (best[r] < best[r - 1]) { unsigned long long tm = best[r]; best[r] = best[r - 1]; best[r - 1] = tm; }
        }
    }
    __shared__ unsigned long long sb[5 * 256], red[256], winner;
    int t = threadIdx.x;
    #pragma unroll
    for (int r = 0; r < 5; r++) sb[r * 256 + t] = best[r];
    __syncthreads();
    for (int round = 0; round < 5; round++) {
        unsigned long long mn = ~0ull;
        #pragma unroll
        for (int r = 0; r < 5; r++) mn = ullmin2(mn, sb[r * 256 + t]);
        red[t] = mn; __syncthreads();
        for (int s = 128; s > 0; s >>= 1) { if (t < s) red[t] = ullmin2(red[t], red[t + s]); __syncthreads(); }
        if (t == 0) { winner = red[0]; g_btop[blockIdx.x * 5 + round] = red[0]; }
        __syncthreads();
        unsigned long long wv = winner;
        #pragma unroll
        for (int r = 0; r < 5; r++) if (sb[r * 256 + t] == wv) sb[r * 256 + t] = ~0ull;
        __syncthreads();
    }
}

// ---------------- 8. top-5 final merge ----------------
__global__ void k_topfinal() {
    __shared__ unsigned long long sb[320], red[256], winner;
    int t = threadIdx.x;  // 256
    sb[t] = g_btop[t];
    if (t < 64) sb[256 + t] = g_btop[256 + t];
    __syncthreads();
    for (int round = 0; round < 5; round++) {
        unsigned long long mn = sb[t];
        if (t < 64) mn = ullmin2(mn, sb[256 + t]);
        red[t] = mn; __syncthreads();
        for (int s = 128; s > 0; s >>= 1) { if (t < s) red[t] = ullmin2(red[t], red[t + s]); __syncthreads(); }
        if (t == 0) { winner = red[0]; g_nn[round] = (int)(red[0] & 0xffffffffu); }
        __syncthreads();
        unsigned long long wv = winner;
        if (sb[t] == wv) sb[t] = ~0ull;
        if (t < 64 && sb[256 + t] == wv) sb[256 + t] = ~0ull;
        __syncthreads();
    }
}

// ---------------- 9. scalar s ----------------
__global__ void k_scalar(const float* __restrict__ lib, float* __restrict__ out, int write_s) {
    __shared__ float red[6][128];
    int t = threadIdx.x;  // 128
    int sidx = g_sidx, msi = g_mstar_idx;
    int nn[5];
    #pragma unroll
    for (int i = 0; i < 5; i++) nn[i] = g_nn[i];
    float ss[6] = {0.f, 0.f, 0.f, 0.f, 0.f, 0.f};
    #pragma unroll
    for (int j = 0; j < 3; j++) {
        int col = t + 128 * j;
        float p = g_patch_n[sidx * DIM + col];
        float d0 = p - lib[(size_t)msi * DIM + col];
        ss[0] += d0 * d0;
        #pragma unroll
        for (int i = 0; i < 5; i++) {
            float d = p - lib[(size_t)nn[i] * DIM + col];
            ss[1 + i] += d * d;
        }
    }
    #pragma unroll
    for (int q = 0; q < 6; q++) red[q][t] = ss[q];
    __syncthreads();
    for (int s = 64; s > 0; s >>= 1) {
        if (t < s) {
            #pragma unroll
            for (int q = 0; q < 6; q++) red[q][t] += red[q][t + s];
        }
        __syncthreads();
    }
    if (t == 0 && write_s) {
        float num = expf(sqrtf(red[0][0]));
        float den = 0.f;
        #pragma unroll
        for (int i = 0; i < 5; i++) den += expf(sqrtf(red[1 + i][0]));
        out[0] = (1.f - num / den) * g_sstar;
    }
}

// ---------------- 10. bilinear 26 -> 224 ----------------
__global__ void k_upsample() {
    int x = blockIdx.x * 32 + threadIdx.x;
    int y = blockIdx.y * 8 + threadIdx.y;
    if (x >= IMG || y >= IMG) return;
    const float scale = 26.f / 224.f;
    float sx = (x + 0.5f) * scale - 0.5f;
    float sy = (y + 0.5f) * scale - 0.5f;
    int x0 = (int)floorf(sx), y0 = (int)floorf(sy);
    float fx = sx - x0, fy = sy - y0;
    int x0c = min(max(x0, 0), 25), x1c = min(max(x0 + 1, 0), 25);
    int y0c = min(max(y0, 0), 25), y1c = min(max(y0 + 1, 0), 25);
    float v00 = g_minval[y0c * 26 + x0c], v01 = g_minval[y0c * 26 + x1c];
    float v10 = g_minval[y1c * 26 + x0c], v11 = g_minval[y1c * 26 + x1c];
    float top = v00 + fx * (v01 - v00), bot = v10 + fx * (v11 - v10);
    g_map_a[y * IMG + x] = top + fy * (bot - top);
}

__device__ __forceinline__ int reflect_idx(int j) {
    if (j < 0) j = -j;
    if (j > IMG - 1) j = 2 * (IMG - 1) - j;
    return j;
}
__device__ __forceinline__ void blur_weights(float* w) {
    float s = 0.f;
    #pragma unroll
    for (int i = 0; i < 33; i++) {
        float xx = (float)(i - KRAD) / SIGMA;
        w[i] = expf(-0.5f * xx * xx); s += w[i];
    }
    float inv = 1.f / s;
    #pragma unroll
    for (int i = 0; i < 33; i++) w[i] *= inv;
}
__global__ void k_blur_v() {
    int x = blockIdx.x * 32 + threadIdx.x;
    int y = blockIdx.y * 8 + threadIdx.y;
    if (x >= IMG || y >= IMG) return;
    float w[33]; blur_weights(w);
    float acc = 0.f;
    #pragma unroll
    for (int i = 0; i < 33; i++) acc += w[i] * g_map_a[reflect_idx(y + i - KRAD) * IMG + x];
    g_map_b[y * IMG + x] = acc;
}
__global__ void k_blur_h(float* __restrict__ out) {
    int x = blockIdx.x * 32 + threadIdx.x;
    int y = blockIdx.y * 8 + threadIdx.y;
    if (x >= IMG || y >= IMG) return;
    float w[33]; blur_weights(w);
    float acc = 0.f;
    #pragma unroll
    for (int i = 0; i < 33; i++) acc += w[i] * g_map_b[y * IMG + reflect_idx(x + i - KRAD)];
    out[y * IMG + x] = acc;
}

extern "C" void kernel_launch(void* const* d_in, const int* in_sizes, int n_in,
                              void* d_out, int out_size) {
    const float* patch = (const float*)d_in[0];
    const float* lib   = (const float*)d_in[1];
    if (n_in >= 2 && in_sizes[0] != N_PATCH * DIM) {
        patch = (const float*)d_in[1]; lib = (const float*)d_in[0];
    }
    float* out = (float*)d_out;
    int ofs = out_size - IMG * IMG;
    if (ofs < 0) ofs = 0;

    static int smem_set = 0;
    if (!smem_set) {
        cudaFuncSetAttribute(k_main, cudaFuncAttributeMaxDynamicSharedMemorySize, SMEM_MAIN);
        smem_set = 1;
    }

    k_prep_patch<<<NPAD, 128>>>(patch);
    k_prep_lib<<<M_LIB / 8, 256>>>(lib);
    k_init<<<1, 768>>>();
    k_main<<<148, 512, SMEM_MAIN>>>();
    k_nmin<<<1, 1024>>>();
    k_pass2<<<M_LIB / 8, 256>>>();
    k_topscan<<<64, 256>>>();
    k_topfinal<<<1, 256>>>();
    k_scalar<<<1, 128>>>(lib, out, ofs > 0 ? 1 : 0);
    dim3 blk(32, 8), grd(7, 28);
    k_upsample<<<grd, blk>>>();
    k_blur_v<<<grd, blk>>>();
    k_blur_h<<<grd, blk>>>(out + ofs);
}

// round 5
// speedup vs baseline: 1.4148x; 1.1395x over previous
#include <cuda_runtime.h>
#include <cuda_bf16.h>
#include <math.h>
#include <stdint.h>

#define M_LIB   200000
#define N_PATCH 676
#define NPAD    768
#define DIM     384
#define IMG     224
#define SIGMA   4.0f
#define KRAD    16

#define STRIPE  5440            // 64 * 85 rows per CTA stripe; 37 stripes
#define NITERS  170             // 85 tiles * 2 k-halves
#define STG_BYTES (64*384)      // one stage: 64 rows x 192 k-elems bf16
#define SM_P    0               // patch chunk 192 x 768B = 147456
#define SM_L    147456
#define SM_MIN  (SM_L + 3*STG_BYTES)   // 221184
#define SMEM_MAIN (SM_MIN + 192*8)     // 222720

// ---------------- device scratch ----------------
__device__ __align__(16) __nv_bfloat16 g_lib_bf16[(size_t)M_LIB * DIM];
__device__ float g_ln[M_LIB];
__device__ float g_patch_n[N_PATCH * DIM];
__device__ __align__(16) __nv_bfloat16 g_patch_bf16[NPAD * DIM];
__device__ float g_pn[N_PATCH];
__device__ unsigned long long g_minbuf[NPAD];
__device__ float g_minval[N_PATCH];
__device__ int   g_sidx;
__device__ int   g_mstar_idx;
__device__ float g_sstar;
__device__ float g_d2star[M_LIB];
__device__ unsigned long long g_btop[64 * 5];
__device__ int   g_nn[5];
__device__ float g_map_a[IMG * IMG];
__device__ float g_map_b[IMG * IMG];

// ---------------- helpers ----------------
__device__ __forceinline__ unsigned fordu(float f) {
    unsigned u = __float_as_uint(f);
    return (u & 0x80000000u) ? ~u : (u | 0x80000000u);
}
__device__ __forceinline__ float fordu_inv(unsigned e) {
    return __uint_as_float((e & 0x80000000u) ? (e ^ 0x80000000u) : ~e);
}
__device__ __forceinline__ unsigned long long packkey(float v, int idx) {
    return ((unsigned long long)fordu(v) << 32) | (unsigned)idx;
}
__device__ __forceinline__ unsigned long long ullmin2(unsigned long long a, unsigned long long b) {
    return a < b ? a : b;
}
#define INF_F (__int_as_float(0x7f800000))

__device__ __forceinline__ uint32_t smem_u32(const void* p) {
    return (uint32_t)__cvta_generic_to_shared(p);
}

#define LDSM4(r0,r1,r2,r3,addr) \
    asm volatile("ldmatrix.sync.aligned.m8n8.x4.shared.b16 {%0,%1,%2,%3}, [%4];" \
        : "=r"(r0), "=r"(r1), "=r"(r2), "=r"(r3) : "r"(addr))
#define MMA16816(D,a0,a1,a2,a3,b0,b1) \
    asm volatile("mma.sync.aligned.m16n8k16.row.col.f32.bf16.bf16.f32 " \
        "{%0,%1,%2,%3},{%4,%5,%6,%7},{%8,%9},{%0,%1,%2,%3};" \
        : "+f"((D)[0]), "+f"((D)[1]), "+f"((D)[2]), "+f"((D)[3]) \
        : "r"(a0), "r"(a1), "r"(a2), "r"(a3), "r"(b0), "r"(b1))

__device__ __forceinline__ void cp16(uint32_t dst, const void* src, uint32_t nbytes) {
    asm volatile("cp.async.cg.shared.global [%0], [%1], 16, %2;"
                 :: "r"(dst), "l"(src), "r"(nbytes) : "memory");
}
#define CP_COMMIT() asm volatile("cp.async.commit_group;" ::: "memory")
#define CP_WAIT1()  asm volatile("cp.async.wait_group 1;" ::: "memory")

// ---------------- 1. normalize patch ----------------
__global__ void k_prep_patch(const float* __restrict__ patch) {
    int n = blockIdx.x, t = threadIdx.x;  // 128 thr
    if (n >= N_PATCH) {
        #pragma unroll
        for (int j = 0; j < 3; j++) g_patch_bf16[n * DIM + t + 128 * j] = __float2bfloat16(0.f);
        return;
    }
    __shared__ float red[128];
    float v[3]; float ss = 0.f;
    #pragma unroll
    for (int j = 0; j < 3; j++) { v[j] = patch[(size_t)n * DIM + t + 128 * j]; ss += v[j] * v[j]; }
    red[t] = ss; __syncthreads();
    for (int s = 64; s > 0; s >>= 1) { if (t < s) red[t] += red[t + s]; __syncthreads(); }
    float denom = fmaxf(sqrtf(red[0]), 1e-12f);
    __syncthreads();
    float pn = 0.f;
    #pragma unroll
    for (int j = 0; j < 3; j++) {
        float x = v[j] / denom; pn += x * x;
        g_patch_n[n * DIM + t + 128 * j] = x;
        g_patch_bf16[n * DIM + t + 128 * j] = __float2bfloat16(x);
    }
    red[t] = pn; __syncthreads();
    for (int s = 64; s > 0; s >>= 1) { if (t < s) red[t] += red[t + s]; __syncthreads(); }
    if (t == 0) g_pn[n] = red[0];
}

// ---------------- 2. lib fp32 -> bf16 + ln ----------------
__global__ void k_prep_lib(const float* __restrict__ lib) {
    int w = threadIdx.x >> 5, lane = threadIdx.x & 31;
    int row = blockIdx.x * 8 + w;
    const float4* src = (const float4*)(lib + (size_t)row * DIM);
    __nv_bfloat162* dst = (__nv_bfloat162*)(g_lib_bf16 + (size_t)row * DIM);
    float ss = 0.f;
    #pragma unroll
    for (int j = 0; j < 3; j++) {
        float4 f = src[lane + 32 * j];
        ss += f.x * f.x + f.y * f.y + f.z * f.z + f.w * f.w;
        dst[2 * (lane + 32 * j)]     = __floats2bfloat162_rn(f.x, f.y);
        dst[2 * (lane + 32 * j) + 1] = __floats2bfloat162_rn(f.z, f.w);
    }
    for (int o = 16; o; o >>= 1) ss += __shfl_xor_sync(0xffffffffu, ss, o);
    if (lane == 0) g_ln[row] = ss;
}

__global__ void k_init() {
    for (int i = threadIdx.x; i < NPAD; i += blockDim.x) g_minbuf[i] = ~0ull;
}

// ---------------- 4. fused bf16 HMMA GEMM + per-patch-row max-dot ----------
// grid 148 = 4 n-chunks x 37 stripes; 384 threads = 12 warps as 2 wm x 6 wn.
// Warp tile 32m x 32n: 4 LDSM.x4 per 8 MMA (was 4 per 6).
__global__ void __launch_bounds__(384, 1) k_main() {
    extern __shared__ char sm[];
    const uint32_t smb = smem_u32(sm);
    unsigned long long* sMin = (unsigned long long*)(sm + SM_MIN);
    const int tid = threadIdx.x;
    const int warp = tid >> 5, lane = tid & 31;
    const int nc = blockIdx.x & 3;
    const int mBase = (blockIdx.x >> 2) * STRIPE;

    if (tid < 192) sMin[tid] = ~0ull;

    // --- stage resident patch chunk [192 x 384] bf16, swizzled 768B rows ---
    for (int i = tid; i < 192 * 48; i += 384) {
        int r = i / 48, u = i % 48;
        uint32_t dst = smb + SM_P + r * 768 + (((u ^ (r & 7))) << 4);
        cp16(dst, g_patch_bf16 + (size_t)(nc * 192 + r) * DIM + u * 8, 16);
    }
    CP_COMMIT();

    // --- prologue: stages 0,1 = tile0 half0, half1 ---
    #pragma unroll
    for (int p = 0; p < 2; p++) {
        for (int i = tid; i < 64 * 24; i += 384) {
            int r = i / 24, u = i % 24;
            int g = mBase + r;
            uint32_t dst = smb + SM_L + p * STG_BYTES + r * 384 + (((u ^ (r & 7))) << 4);
            cp16(dst, g_lib_bf16 + (size_t)min(g, M_LIB - 1) * DIM + p * 192 + u * 8,
                 (g < M_LIB) ? 16u : 0u);
        }
        CP_COMMIT();
    }

    // --- per-thread invariants ---
    const int wm = warp & 1, wn = warp >> 1;      // 2 x 6 grid, warp tile 32m x 32n
    const unsigned hiA = (lane >> 4);
    const unsigned hiB = (lane >> 3) & 1;
    unsigned baseA[2], swA[2];
    #pragma unroll
    for (int mf = 0; mf < 2; mf++) {
        unsigned rA = 32 * wm + 16 * mf + (lane & 15);
        baseA[mf] = rA * 384;
        swA[mf] = rA & 7;
    }
    unsigned pBase[2], swB[2];
    #pragma unroll
    for (int f2 = 0; f2 < 2; f2++) {
        unsigned rB = 32 * wn + 16 * f2 + (lane & 7) + ((lane >> 4) << 3);
        pBase[f2] = smb + SM_P + rB * 768;
        swB[f2] = rB & 7;
    }
    const int g8 = lane >> 2, tig = lane & 3;

    float runV[8]; int runI[8];
    #pragma unroll
    for (int j = 0; j < 8; j++) { runV[j] = -INF_F; runI[j] = 0; }

    float acc[8][4];
    #pragma unroll
    for (int g = 0; g < 8; g++) acc[g][0] = acc[g][1] = acc[g][2] = acc[g][3] = 0.f;

    for (int it = 0; it < NITERS; it++) {
        const int s = it % 3, h = it & 1;
        CP_WAIT1();
        __syncthreads();
        // prefetch it+2 into freed stage
        {
            int nx = it + 2;
            if (nx < NITERS) {
                int sN = nx % 3, hN = nx & 1, mN = mBase + (nx >> 1) * 64;
                for (int i = tid; i < 64 * 24; i += 384) {
                    int r = i / 24, u = i % 24;
                    int g = mN + r;
                    uint32_t dst = smb + SM_L + sN * STG_BYTES + r * 384 + (((u ^ (r & 7))) << 4);
                    cp16(dst, g_lib_bf16 + (size_t)min(g, M_LIB - 1) * DIM + hN * 192 + u * 8,
                         (g < M_LIB) ? 16u : 0u);
                }
            }
            CP_COMMIT();
        }
        // compute this stage: 12 ksteps, warp tile 32m x 32n
        const unsigned stgA = smb + SM_L + s * STG_BYTES;
        const unsigned kb0 = 24 * h + hiB;
        #pragma unroll
        for (int ks = 0; ks < 12; ks++) {
            unsigned a0[4], a1[4];
            unsigned uA = 2 * ks + hiA;
            LDSM4(a0[0], a0[1], a0[2], a0[3], stgA + baseA[0] + (((uA ^ swA[0])) << 4));
            LDSM4(a1[0], a1[1], a1[2], a1[3], stgA + baseA[1] + (((uA ^ swA[1])) << 4));
            #pragma unroll
            for (int f2 = 0; f2 < 2; f2++) {
                unsigned r0, r1, r2, r3;
                unsigned uB = kb0 + 2 * ks;
                LDSM4(r0, r1, r2, r3, pBase[f2] + (((uB ^ swB[f2])) << 4));
                MMA16816(acc[2 * f2],     a0[0], a0[1], a0[2], a0[3], r0, r1);
                MMA16816(acc[2 * f2 + 1], a0[0], a0[1], a0[2], a0[3], r2, r3);
                MMA16816(acc[4 + 2 * f2],     a1[0], a1[1], a1[2], a1[3], r0, r1);
                MMA16816(acc[4 + 2 * f2 + 1], a1[0], a1[1], a1[2], a1[3], r2, r3);
            }
        }
        if (h) {
            // tile epilogue: update per-column running max dot
            int mt = mBase + (it >> 1) * 64;
            #pragma unroll
            for (int g = 0; g < 8; g++) {
                int mf = g >> 2;
                int mlo = mt + 32 * wm + 16 * mf + g8, mhi = mlo + 8;
                bool okLo = mlo < M_LIB, okHi = mhi < M_LIB;
                #pragma unroll
                for (int c = 0; c < 2; c++) {
                    int jj = ((g & 3) << 1) | c;
                    float vlo = acc[g][c], vhi = acc[g][2 + c];
                    if (okLo && vlo > runV[jj]) { runV[jj] = vlo; runI[jj] = mlo; }
                    if (okHi && vhi > runV[jj]) { runV[jj] = vhi; runI[jj] = mhi; }
                }
                acc[g][0] = acc[g][1] = acc[g][2] = acc[g][3] = 0.f;
            }
        }
    }

    // reduce over the 8 lanes sharing each column
    #pragma unroll
    for (int off = 4; off < 32; off <<= 1) {
        #pragma unroll
        for (int j = 0; j < 8; j++) {
            float ov = __shfl_xor_sync(0xffffffffu, runV[j], off);
            int   oi = __shfl_xor_sync(0xffffffffu, runI[j], off);
            if (ov > runV[j]) { runV[j] = ov; runI[j] = oi; }
        }
    }
    if (g8 == 0) {
        #pragma unroll
        for (int jj = 0; jj < 8; jj++) {
            int f2 = jj >> 2, nh = (jj >> 1) & 1, c = jj & 1;
            int col = 32 * wn + 16 * f2 + 8 * nh + 2 * tig + c;
            atomicMin(&sMin[col], packkey(-runV[jj], runI[jj]));
        }
    }
    __syncthreads();
    if (tid < 192) atomicMin(&g_minbuf[nc * 192 + tid], sMin[tid]);
}

// ---------------- 5. min_val per n + argmax over n ----------------
__global__ void k_nmin() {
    int t = threadIdx.x;  // 1024
    __shared__ float rv[1024]; __shared__ int ri[1024];
    float mv = -INF_F; int idx = 0;
    if (t < N_PATCH) {
        unsigned long long key = g_minbuf[t];
        int mi = (int)(key & 0xffffffffu);
        float v = fordu_inv((unsigned)(key >> 32));   // = -max_dot
        float d2 = g_pn[t] + g_ln[mi] + 2.f * v;
        mv = sqrtf(fmaxf(d2, 0.f));
        g_minval[t] = mv; idx = t;
    }
    rv[t] = mv; ri[t] = idx; __syncthreads();
    for (int s = 512; s > 0; s >>= 1) {
        if (t < s && rv[t + s] > rv[t]) { rv[t] = rv[t + s]; ri[t] = ri[t + s]; }
        __syncthreads();
    }
    if (t == 0) {
        g_sidx = ri[0]; g_sstar = rv[0];
        g_mstar_idx = (int)(g_minbuf[ri[0]] & 0xffffffffu);
    }
}

// ---------------- 6. d*^2 (shifted) over all lib rows ----------------
__global__ void k_pass2() {
    int w = threadIdx.x >> 5, lane = threadIdx.x & 31;
    int row = blockIdx.x * 8 + w;
    int msi = g_mstar_idx;
    const unsigned* a = (const unsigned*)(g_lib_bf16 + (size_t)row * DIM);
    const unsigned* b = (const unsigned*)(g_lib_bf16 + (size_t)msi * DIM);
    float dot = 0.f;
    #pragma unroll
    for (int j = 0; j < 6; j++) {
        unsigned ua = a[lane + 32 * j], ub = b[lane + 32 * j];
        float2 fa = __bfloat1622float2(*(__nv_bfloat162*)&ua);
        float2 fb = __bfloat1622float2(*(__nv_bfloat162*)&ub);
        dot = fmaf(fa.x, fb.x, dot); dot = fmaf(fa.y, fb.y, dot);
    }
    for (int o = 16; o; o >>= 1) dot += __shfl_xor_sync(0xffffffffu, dot, o);
    if (lane == 0) g_d2star[row] = g_ln[row] - 2.f * dot;
}

// ---------------- 7. top-5 smallest, block stage ----------------
__global__ void k_topscan() {
    unsigned long long best[5];
    #pragma unroll
    for (int r = 0; r < 5; r++) best[r] = ~0ull;
    for (int m = blockIdx.x * 256 + threadIdx.x; m < M_LIB; m += 64 * 256) {
        unsigned long long key = packkey(g_d2star[m], m);
        if (key < best[4]) {
            best[4] = key;
            #pragma unroll
            for (int r = 4; r > 0; r--)
                if (best[r] < best[r - 1]) { unsigned long long tm = best[r]; best[r] = best[r - 1]; best[r - 1] = tm; }
        }
    }
    __shared__ unsigned long long sb[5 * 256], red[256], winner;
    int t = threadIdx.x;
    #pragma unroll
    for (int r = 0; r < 5; r++) sb[r * 256 + t] = best[r];
    __syncthreads();
    for (int round = 0; round < 5; round++) {
        unsigned long long mn = ~0ull;
        #pragma unroll
        for (int r = 0; r < 5; r++) mn = ullmin2(mn, sb[r * 256 + t]);
        red[t] = mn; __syncthreads();
        for (int s = 128; s > 0; s >>= 1) { if (t < s) red[t] = ullmin2(red[t], red[t + s]); __syncthreads(); }
        if (t == 0) { winner = red[0]; g_btop[blockIdx.x * 5 + round] = red[0]; }
        __syncthreads();
        unsigned long long wv = winner;
        #pragma unroll
        for (int r = 0; r < 5; r++) if (sb[r * 256 + t] == wv) sb[r * 256 + t] = ~0ull;
        __syncthreads();
    }
}

// ---------------- 8. top-5 final merge ----------------
__global__ void k_topfinal() {
    __shared__ unsigned long long sb[320], red[256], winner;
    int t = threadIdx.x;  // 256
    sb[t] = g_btop[t];
    if (t < 64) sb[256 + t] = g_btop[256 + t];
    __syncthreads();
    for (int round = 0; round < 5; round++) {
        unsigned long long mn = sb[t];
        if (t < 64) mn = ullmin2(mn, sb[256 + t]);
        red[t] = mn; __syncthreads();
        for (int s = 128; s > 0; s >>= 1) { if (t < s) red[t] = ullmin2(red[t], red[t + s]); __syncthreads(); }
        if (t == 0) { winner = red[0]; g_nn[round] = (int)(red[0] & 0xffffffffu); }
        __syncthreads();
        unsigned long long wv = winner;
        if (sb[t] == wv) sb[t] = ~0ull;
        if (t < 64 && sb[256 + t] == wv) sb[256 + t] = ~0ull;
        __syncthreads();
    }
}

// ---------------- 9. scalar s ----------------
__global__ void k_scalar(const float* __restrict__ lib, float* __restrict__ out, int write_s) {
    __shared__ float red[6][128];
    int t = threadIdx.x;  // 128
    int sidx = g_sidx, msi = g_mstar_idx;
    int nn[5];
    #pragma unroll
    for (int i = 0; i < 5; i++) nn[i] = g_nn[i];
    float ss[6] = {0.f, 0.f, 0.f, 0.f, 0.f, 0.f};
    #pragma unroll
    for (int j = 0; j < 3; j++) {
        int col = t + 128 * j;
        float p = g_patch_n[sidx * DIM + col];
        float d0 = p - lib[(size_t)msi * DIM + col];
        ss[0] += d0 * d0;
        #pragma unroll
        for (int i = 0; i < 5; i++) {
            float d = p - lib[(size_t)nn[i] * DIM + col];
            ss[1 + i] += d * d;
        }
    }
    #pragma unroll
    for (int q = 0; q < 6; q++) red[q][t] = ss[q];
    __syncthreads();
    for (int s = 64; s > 0; s >>= 1) {
        if (t < s) {
            #pragma unroll
            for (int q = 0; q < 6; q++) red[q][t] += red[q][t + s];
        }
        __syncthreads();
    }
    if (t == 0 && write_s) {
        float num = expf(sqrtf(red[0][0]));
        float den = 0.f;
        #pragma unroll
        for (int i = 0; i < 5; i++) den += expf(sqrtf(red[1 + i][0]));
        out[0] = (1.f - num / den) * g_sstar;
    }
}

// ---------------- 10. bilinear 26 -> 224 ----------------
__global__ void k_upsample() {
    int x = blockIdx.x * 32 + threadIdx.x;
    int y = blockIdx.y * 8 + threadIdx.y;
    if (x >= IMG || y >= IMG) return;
    const float scale = 26.f / 224.f;
    float sx = (x + 0.5f) * scale - 0.5f;
    float sy = (y + 0.5f) * scale - 0.5f;
    int x0 = (int)floorf(sx), y0 = (int)floorf(sy);
    float fx = sx - x0, fy = sy - y0;
    int x0c = min(max(x0, 0), 25), x1c = min(max(x0 + 1, 0), 25);
    int y0c = min(max(y0, 0), 25), y1c = min(max(y0 + 1, 0), 25);
    float v00 = g_minval[y0c * 26 + x0c], v01 = g_minval[y0c * 26 + x1c];
    float v10 = g_minval[y1c * 26 + x0c], v11 = g_minval[y1c * 26 + x1c];
    float top = v00 + fx * (v01 - v00), bot = v10 + fx * (v11 - v10);
    g_map_a[y * IMG + x] = top + fy * (bot - top);
}

__device__ __forceinline__ int reflect_idx(int j) {
    if (j < 0) j = -j;
    if (j > IMG - 1) j = 2 * (IMG - 1) - j;
    return j;
}
__device__ __forceinline__ void blur_weights(float* w) {
    float s = 0.f;
    #pragma unroll
    for (int i = 0; i < 33; i++) {
        float xx = (float)(i - KRAD) / SIGMA;
        w[i] = expf(-0.5f * xx * xx); s += w[i];
    }
    float inv = 1.f / s;
    #pragma unroll
    for (int i = 0; i < 33; i++) w[i] *= inv;
}
__global__ void k_blur_v() {
    int x = blockIdx.x * 32 + threadIdx.x;
    int y = blockIdx.y * 8 + threadIdx.y;
    if (x >= IMG || y >= IMG) return;
    float w[33]; blur_weights(w);
    float acc = 0.f;
    #pragma unroll
    for (int i = 0; i < 33; i++) acc += w[i] * g_map_a[reflect_idx(y + i - KRAD) * IMG + x];
    g_map_b[y * IMG + x] = acc;
}
__global__ void k_blur_h(float* __restrict__ out) {
    int x = blockIdx.x * 32 + threadIdx.x;
    int y = blockIdx.y * 8 + threadIdx.y;
    if (x >= IMG || y >= IMG) return;
    float w[33]; blur_weights(w);
    float acc = 0.f;
    #pragma unroll
    for (int i = 0; i < 33; i++) acc += w[i] * g_map_b[y * IMG + reflect_idx(x + i - KRAD)];
    out[y * IMG + x] = acc;
}

extern "C" void kernel_launch(void* const* d_in, const int* in_sizes, int n_in,
                              void* d_out, int out_size) {
    const float* patch = (const float*)d_in[0];
    const float* lib   = (const float*)d_in[1];
    if (n_in >= 2 && in_sizes[0] != N_PATCH * DIM) {
        patch = (const float*)d_in[1]; lib = (const float*)d_in[0];
    }
    float* out = (float*)d_out;
    int ofs = out_size - IMG * IMG;
    if (ofs < 0) ofs = 0;

    static int smem_set = 0;
    if (!smem_set) {
        cudaFuncSetAttribute(k_main, cudaFuncAttributeMaxDynamicSharedMemorySize, SMEM_MAIN);
        smem_set = 1;
    }

    k_prep_patch<<<NPAD, 128>>>(patch);
    k_prep_lib<<<M_LIB / 8, 256>>>(lib);
    k_init<<<1, 768>>>();
    k_main<<<148, 384, SMEM_MAIN>>>();
    k_nmin<<<1, 1024>>>();
    k_pass2<<<M_LIB / 8, 256>>>();
    k_topscan<<<64, 256>>>();
    k_topfinal<<<1, 256>>>();
    k_scalar<<<1, 128>>>(lib, out, ofs > 0 ? 1 : 0);
    dim3 blk(32, 8), grd(7, 28);
    k_upsample<<<grd, blk>>>();
    k_blur_v<<<grd, blk>>>();
    k_blur_h<<<grd, blk>>>(out + ofs);
}